// round 13
// baseline (speedup 1.0000x reference)
#include <cuda_runtime.h>
#include <cuda_bf16.h>
#include <stdint.h>
#include <math.h>

#define NATOMS 10000
#define NEDGE  64000
#define BG     128
#define HID    600
#define NG     50
#define NL     6
#define HID4   150     // HID/4
#define KP_H   608     // HID padded to 16
#define KP_G   64      // NG padded to 16
#define TAB    4096    // W(d) table resolution
#define DMAX   8.6603f // > sqrt(75) = max possible distance
#define TDELTA (DMAX / (TAB - 1))

// ------------------------- scratch (static device globals) -------------------
__device__ int   g_ei0[NEDGE];
__device__ float g_efr[NEDGE];
__device__ float g_rbftab[TAB * KP_G];        // tf32-rounded
__device__ float g_Ctab  [TAB];
__device__ float g_F1tab [(size_t)NL * TAB * HID];
__device__ float g_Wtab  [(size_t)NL * TAB * HID];
__device__ float g_h  [NATOMS * HID];
__device__ float g_xjp[NATOMS * HID];
__device__ float g_agg[NATOMS * HID];
__device__ float g_t1 [NATOMS * HID];
__device__ float g_pool[BG * HID];

// tf32-rounded transposed weights (stored as f32): layout [N][Kpad]
__device__ float g_w1t [NL * HID * KP_G];
__device__ float g_w2t [NL * HID * KP_H];
__device__ float g_l1t [NL * HID * KP_H];
__device__ float g_l2t [NL * HID * KP_H];
__device__ float g_ilt [NL * HID * KP_H];
__device__ float g_pwt [HID * KP_H];

// ------------------------- helpers ------------------------------------------
__device__ __forceinline__ float sspf(float x) {
    float ax = fabsf(x);
    return fmaxf(x, 0.0f) + log1pf(expf(-ax)) - 0.69314718055994531f;
}

__device__ __forceinline__ float to_tf32(float x) {
    float r;
    asm("cvt.rna.tf32.f32 %0, %1;" : "=f"(r) : "f"(x));
    return r;
}

// ------------------------- edge geometry -> table coords ---------------------
__global__ void edge_geom_kernel(const float* __restrict__ pos,
                                 const int* __restrict__ src,
                                 const int* __restrict__ dst) {
    int e = blockIdx.x * blockDim.x + threadIdx.x;
    if (e >= NEDGE) return;
    int s = src[e], t = dst[e];
    float dx = pos[s*3+0] - pos[t*3+0];
    float dy = pos[s*3+1] - pos[t*3+1];
    float dz = pos[s*3+2] - pos[t*3+2];
    float d = sqrtf(dx*dx + dy*dy + dz*dz + 1e-12f);
    float tt = d * (1.0f / TDELTA);
    int i0 = (int)tt;
    if (i0 > TAB - 2) i0 = TAB - 2;
    g_ei0[e] = i0;
    g_efr[e] = tt - (float)i0;
}

// ------------------------- rbf + cutoff table (tf32-rounded) -----------------
__global__ void rbftab_kernel() {
    int i = blockIdx.x * blockDim.x + threadIdx.x;
    if (i >= TAB * KP_G) return;
    int r = i / KP_G;
    int g = i - r * KP_G;
    float d = (float)r * TDELTA;
    float v = 0.0f;
    if (g < NG) {
        float off = (float)g * (10.0f / 49.0f);
        float dd  = d - off;
        v = expf(-12.005f * dd * dd);
    }
    g_rbftab[i] = to_tf32(v);
    if (g == 0)
        g_Ctab[r] = 0.5f * (cosf(d * 0.31415926535897931f) + 1.0f);
}

__global__ void emb_kernel(const int* __restrict__ z, const float* __restrict__ emb) {
    int i = blockIdx.x * blockDim.x + threadIdx.x;
    if (i >= NATOMS * HID) return;
    int n = i / HID;
    int j = i - n * HID;
    g_h[i] = to_tf32(emb[z[n] * HID + j]);
}

// round a buffer in place to tf32 (float4 vectorized)
__global__ void round4_kernel(float* __restrict__ p, int n4) {
    int i = blockIdx.x * blockDim.x + threadIdx.x;
    if (i >= n4) return;
    float4 v = ((float4*)p)[i];
    v.x = to_tf32(v.x); v.y = to_tf32(v.y);
    v.z = to_tf32(v.z); v.w = to_tf32(v.w);
    ((float4*)p)[i] = v;
}

// ------------------------- weight transpose + tf32 round (batched) -----------
__global__ void convt_kernel(const float* __restrict__ in, float* __restrict__ out,
                             int K, int N, int Kpad,
                             long in_stride, long out_stride) {
    in  += (size_t)blockIdx.z * in_stride;
    out += (size_t)blockIdx.z * out_stride;
    __shared__ float tile[32][33];
    int kb = blockIdx.x * 32, nb = blockIdx.y * 32;
    int tx = threadIdx.x, ty = threadIdx.y;
    #pragma unroll
    for (int i = ty; i < 32; i += 8) {
        int k = kb + i, n = nb + tx;
        tile[i][tx] = (k < K && n < N) ? in[(size_t)k * N + n] : 0.0f;
    }
    __syncthreads();
    #pragma unroll
    for (int i = ty; i < 32; i += 8) {
        int n = nb + i, k = kb + tx;
        if (n < N && k < Kpad) out[(size_t)n * Kpad + k] = to_tf32(tile[tx][i]);
    }
}

// ------------------------- tf32 tensor-core GEMM (cp.async, grid.z batched) --
// Per batch z: C[M,N] = ep( A[M,K] @ Bt[N,Kpad] ), pointers offset by strides.
// CTA 128x128x16, 8 warps (2x4), warp tile 64x32, mma.m16n8k8, fp32 acc.
#define TBM 128
#define TBN 128
#define TBK 16
#define SA  20
#define SB  20

__global__ __launch_bounds__(256, 3)
void gemm_tc_kernel(const float* __restrict__ A,
                    const float* __restrict__ Bt,
                    const float* __restrict__ bias,
                    const float* __restrict__ rowscale,
                    const float* __restrict__ addsrc,
                    float* __restrict__ C,
                    float* __restrict__ zbuf,
                    int M, int N, int K, int Kpad, int do_ssp, int do_round,
                    long strideA, long strideB, long strideC, long strideBias) {
    A  += (size_t)blockIdx.z * strideA;
    Bt += (size_t)blockIdx.z * strideB;
    C  += (size_t)blockIdx.z * strideC;
    if (bias) bias += (size_t)blockIdx.z * strideBias;

    __shared__ __align__(16) float As[2][TBM * SA];
    __shared__ __align__(16) float Bs[2][TBN * SB];

    const int bm = blockIdx.y * TBM;
    const int bn = blockIdx.x * TBN;
    const int tid  = threadIdx.x;
    const int lane = tid & 31;
    const int warp = tid >> 5;
    const int wm0 = (warp >> 2) * 64;
    const int wn0 = (warp & 3) * 32;
    const int gid = lane >> 2;
    const int lk  = lane & 3;

    const int srow = tid >> 1;
    const int scol = (tid & 1) * 8;

    const uint32_t sAbase = (uint32_t)__cvta_generic_to_shared(&As[0][0]);
    const uint32_t sBbase = (uint32_t)__cvta_generic_to_shared(&Bs[0][0]);

    float acc[4][4][4] = {};

    const int nsteps = Kpad / TBK;

    auto stage = [&](int k0, int buf) {
        int gm = bm + srow;
        uint32_t da = sAbase + (uint32_t)((buf * TBM * SA + srow * SA + scol) * 4);
        const float* arow = A + (size_t)(gm < M ? gm : 0) * K;
        #pragma unroll
        for (int h2 = 0; h2 < 2; h2++) {
            int gk = k0 + scol + h2 * 4;
            int nb = (gm < M) ? (K - gk) * 4 : 0;
            nb = nb < 0 ? 0 : (nb > 16 ? 16 : nb);
            const float* gp = arow + (nb > 0 ? gk : 0);
            asm volatile("cp.async.cg.shared.global [%0], [%1], 16, %2;"
                         :: "r"(da + h2 * 16), "l"(gp), "r"(nb));
        }
        int gn = bn + srow;
        uint32_t db = sBbase + (uint32_t)((buf * TBN * SB + srow * SB + scol) * 4);
        const float* brow = Bt + (size_t)(gn < N ? gn : 0) * Kpad + k0 + scol;
        int nbB = (gn < N) ? 16 : 0;
        #pragma unroll
        for (int h2 = 0; h2 < 2; h2++) {
            asm volatile("cp.async.cg.shared.global [%0], [%1], 16, %2;"
                         :: "r"(db + h2 * 16), "l"(brow + h2 * 4), "r"(nbB));
        }
        asm volatile("cp.async.commit_group;" ::: "memory");
    };

    stage(0, 0);
    asm volatile("cp.async.wait_group 0;" ::: "memory");
    __syncthreads();

    for (int s = 0; s < nsteps; s++) {
        if (s + 1 < nsteps) stage((s + 1) * TBK, (s + 1) & 1);

        const float* as = As[s & 1];
        const float* bs = Bs[s & 1];
        #pragma unroll
        for (int ks = 0; ks < 2; ks++) {
            int kof = ks * 8 + lk;
            unsigned int af[4][4], bf[4][2];
            #pragma unroll
            for (int mt = 0; mt < 4; mt++) {
                int r = wm0 + mt * 16 + gid;
                af[mt][0] = __float_as_uint(as[r * SA + kof]);
                af[mt][1] = __float_as_uint(as[(r + 8) * SA + kof]);
                af[mt][2] = __float_as_uint(as[r * SA + kof + 4]);
                af[mt][3] = __float_as_uint(as[(r + 8) * SA + kof + 4]);
            }
            #pragma unroll
            for (int nt = 0; nt < 4; nt++) {
                int c = wn0 + nt * 8 + gid;
                bf[nt][0] = __float_as_uint(bs[c * SB + kof]);
                bf[nt][1] = __float_as_uint(bs[c * SB + kof + 4]);
            }
            #pragma unroll
            for (int mt = 0; mt < 4; mt++)
                #pragma unroll
                for (int nt = 0; nt < 4; nt++) {
                    asm volatile(
                        "mma.sync.aligned.m16n8k8.row.col.f32.tf32.tf32.f32 "
                        "{%0,%1,%2,%3}, {%4,%5,%6,%7}, {%8,%9}, {%0,%1,%2,%3};"
                        : "+f"(acc[mt][nt][0]), "+f"(acc[mt][nt][1]),
                          "+f"(acc[mt][nt][2]), "+f"(acc[mt][nt][3])
                        : "r"(af[mt][0]), "r"(af[mt][1]), "r"(af[mt][2]), "r"(af[mt][3]),
                          "r"(bf[nt][0]), "r"(bf[nt][1]));
                }
        }
        if (s + 1 < nsteps)
            asm volatile("cp.async.wait_group 0;" ::: "memory");
        __syncthreads();
    }

    // ---- epilogue ----
    #pragma unroll
    for (int mt = 0; mt < 4; mt++) {
        #pragma unroll
        for (int rr = 0; rr < 2; rr++) {
            int gm = bm + wm0 + mt * 16 + gid + rr * 8;
            if (gm >= M) continue;
            float rs = rowscale ? rowscale[gm] : 1.0f;
            #pragma unroll
            for (int nt = 0; nt < 4; nt++) {
                #pragma unroll
                for (int cc = 0; cc < 2; cc++) {
                    int gn = bn + wn0 + nt * 8 + lk * 2 + cc;
                    if (gn >= N) continue;
                    float v = acc[mt][nt][rr * 2 + cc];
                    if (bias) v += bias[gn];
                    if (do_ssp) v = sspf(v);
                    if (rowscale) v *= rs;
                    if (addsrc) v += addsrc[(size_t)gm * N + gn];
                    if (do_round) v = to_tf32(v);
                    C[(size_t)gm * N + gn] = v;
                    if (zbuf) zbuf[(size_t)gm * N + gn] = 0.0f;
                }
            }
        }
    }
}

// ------------------------- CFConv scatter with table interpolation -----------
__global__ void scatter_kernel(const int* __restrict__ src,
                               const int* __restrict__ dst,
                               const float* __restrict__ Wtab) {
    int i = blockIdx.x * blockDim.x + threadIdx.x;
    if (i >= NEDGE * HID4) return;
    int e = i / HID4;
    int j = i - e * HID4;
    int s = src[e], d = dst[e];
    int i0 = g_ei0[e];
    float f = g_efr[e];
    const float4* tp = (const float4*)Wtab;
    const float4* xp = (const float4*)g_xjp;
    float4 w0 = tp[(size_t)i0 * HID4 + j];
    float4 w1 = tp[(size_t)(i0 + 1) * HID4 + j];
    float4 x  = xp[(size_t)s * HID4 + j];
    float4 v;
    v.x = x.x * fmaf(f, w1.x - w0.x, w0.x);
    v.y = x.y * fmaf(f, w1.y - w0.y, w0.y);
    v.z = x.z * fmaf(f, w1.z - w0.z, w0.z);
    v.w = x.w * fmaf(f, w1.w - w0.w, w0.w);
    float* a = g_agg + ((size_t)d * HID + j * 4);
    asm volatile("red.global.add.v4.f32 [%0], {%1,%2,%3,%4};"
                 :: "l"(a), "f"(v.x), "f"(v.y), "f"(v.z), "f"(v.w) : "memory");
}

// ------------------------- segment-mean pool (rounded for final GEMM) --------
__global__ void pool_kernel(const int* __restrict__ batch) {
    int b = blockIdx.x;
    int t = threadIdx.x;
    int lo = 0, hi = NATOMS;
    while (lo < hi) { int mid = (lo + hi) >> 1; if (batch[mid] < b) lo = mid + 1; else hi = mid; }
    int start = lo;
    lo = start; hi = NATOMS;
    while (lo < hi) { int mid = (lo + hi) >> 1; if (batch[mid] <= b) lo = mid + 1; else hi = mid; }
    int end = lo;
    int cnt = end - start;
    float inv = cnt > 0 ? 1.0f / (float)cnt : 0.0f;
    if (t < HID) {
        float s = 0.0f;
        for (int n = start; n < end; n++) s += g_h[n * HID + t];
        g_pool[b * HID + t] = to_tf32(s * inv);
    }
}

// ------------------------- host orchestration --------------------------------
static inline void launch_gemm(const float* A, const float* Bt, const float* bias,
                               const float* rowscale, const float* addsrc,
                               float* C, float* zbuf, int M, int N, int K, int Kpad,
                               int do_ssp, int do_round,
                               int nbatch = 1, long sA = 0, long sB = 0,
                               long sC = 0, long sBias = 0) {
    dim3 grid((N + TBN - 1) / TBN, (M + TBM - 1) / TBM, nbatch);
    gemm_tc_kernel<<<grid, 256>>>(A, Bt, bias, rowscale, addsrc, C, zbuf,
                                  M, N, K, Kpad, do_ssp, do_round,
                                  sA, sB, sC, sBias);
}

static inline void launch_convt(const float* in, float* out, int K, int N, int Kpad,
                                long in_stride, long out_stride, int nbatch) {
    dim3 grid((Kpad + 31) / 32, (N + 31) / 32, nbatch);
    convt_kernel<<<grid, dim3(32, 8)>>>(in, out, K, N, Kpad, in_stride, out_stride);
}

extern "C" void kernel_launch(void* const* d_in, const int* in_sizes, int n_in,
                              void* d_out, int out_size) {
    const int*   z     = (const int*)  d_in[0];
    const float* pos   = (const float*)d_in[1];
    const int*   batch = (const int*)  d_in[2];
    const int*   ei    = (const int*)  d_in[3];
    const float* emb   = (const float*)d_in[4];
    const float* w1    = (const float*)d_in[5];
    const float* b1    = (const float*)d_in[6];
    const float* w2    = (const float*)d_in[7];
    const float* b2    = (const float*)d_in[8];
    const float* l1w   = (const float*)d_in[9];
    const float* l2w   = (const float*)d_in[10];
    const float* l2b   = (const float*)d_in[11];
    const float* ilw   = (const float*)d_in[12];
    const float* ilb   = (const float*)d_in[13];
    const float* pw    = (const float*)d_in[14];
    const float* pb    = (const float*)d_in[15];
    (void)in_sizes; (void)n_in; (void)out_size;

    const int* src = ei;
    const int* dst = ei + NEDGE;

    float *prbftab, *pCtab, *pF1tab, *pWtab, *ph, *pxjp, *pagg, *pt1, *ppool;
    float *pw1t, *pw2t, *pl1t, *pl2t, *pilt, *ppwt;
    cudaGetSymbolAddress((void**)&prbftab, g_rbftab);
    cudaGetSymbolAddress((void**)&pCtab,  g_Ctab);
    cudaGetSymbolAddress((void**)&pF1tab, g_F1tab);
    cudaGetSymbolAddress((void**)&pWtab,  g_Wtab);
    cudaGetSymbolAddress((void**)&ph,     g_h);
    cudaGetSymbolAddress((void**)&pxjp,   g_xjp);
    cudaGetSymbolAddress((void**)&pagg,   g_agg);
    cudaGetSymbolAddress((void**)&pt1,    g_t1);
    cudaGetSymbolAddress((void**)&ppool,  g_pool);
    cudaGetSymbolAddress((void**)&pw1t,   g_w1t);
    cudaGetSymbolAddress((void**)&pw2t,   g_w2t);
    cudaGetSymbolAddress((void**)&pl1t,   g_l1t);
    cudaGetSymbolAddress((void**)&pl2t,   g_l2t);
    cudaGetSymbolAddress((void**)&pilt,   g_ilt);
    cudaGetSymbolAddress((void**)&ppwt,   g_pwt);

    // weight transpose + tf32 rounding (batched over layers)
    launch_convt(w1,  pw1t, NG,  HID, KP_G, (long)NG  * HID, (long)HID * KP_G, NL);
    launch_convt(w2,  pw2t, HID, HID, KP_H, (long)HID * HID, (long)HID * KP_H, NL);
    launch_convt(l1w, pl1t, HID, HID, KP_H, (long)HID * HID, (long)HID * KP_H, NL);
    launch_convt(l2w, pl2t, HID, HID, KP_H, (long)HID * HID, (long)HID * KP_H, NL);
    launch_convt(ilw, pilt, HID, HID, KP_H, (long)HID * HID, (long)HID * KP_H, NL);
    launch_convt(pw,  ppwt, HID, HID, KP_H, 0, 0, 1);

    // edge table coords + rbf table + embedding init
    edge_geom_kernel<<<(NEDGE + 255) / 256, 256>>>(pos, src, dst);
    rbftab_kernel<<<(TAB * KP_G + 255) / 256, 256>>>();
    emb_kernel<<<(NATOMS * HID + 255) / 256, 256>>>(z, emb);

    // ---- precompute all layers' W(d) tables (independent of node chain) ----
    // F1tab[k] = ssp(rbftab @ w1[k] + b1[k]), tf32-rounded        [NL,TAB,H]
    launch_gemm(prbftab, pw1t, b1, nullptr, nullptr, pF1tab, nullptr,
                TAB, HID, KP_G, KP_G, 1, 1,
                NL, 0, (long)HID * KP_G, (long)TAB * HID, HID);
    // Wtab[k] = (F1tab[k] @ w2[k] + b2[k]) * Ctab                 [NL,TAB,H]
    launch_gemm(pF1tab, pw2t, b2, pCtab, nullptr, pWtab, nullptr,
                TAB, HID, HID, KP_H, 0, 0,
                NL, (long)TAB * HID, (long)HID * KP_H, (long)TAB * HID, HID);

    for (int k = 0; k < NL; k++) {
        const float* l2bk = l2b + (size_t)k * HID;
        const float* ilbk = ilb + (size_t)k * HID;
        const float* l1tk = pl1t + (size_t)k * HID * KP_H;
        const float* l2tk = pl2t + (size_t)k * HID * KP_H;
        const float* iltk = pilt + (size_t)k * HID * KP_H;
        const float* Wtabk = pWtab + (size_t)k * TAB * HID;

        // xjp = h @ lin1  (also zeroes agg in epilogue)          [N,H]
        launch_gemm(ph, l1tk, nullptr, nullptr, nullptr, pxjp, pagg,
                    NATOMS, HID, HID, KP_H, 0, 0);
        // agg += scatter(xjp[src] * W(d) -> dst)                 [N,H]
        scatter_kernel<<<(NEDGE * HID4 + 255) / 256, 256>>>(src, dst, Wtabk);
        round4_kernel<<<(NATOMS * HID4 + 255) / 256, 256>>>(pagg, NATOMS * HID4);
        // t1 = ssp(agg @ lin2 + lin2_b), tf32-rounded            [N,H]
        launch_gemm(pagg, l2tk, l2bk, nullptr, nullptr, pt1, nullptr,
                    NATOMS, HID, HID, KP_H, 1, 1);
        // h = h + t1 @ int_lin + int_b, tf32-rounded             [N,H]
        launch_gemm(pt1, iltk, ilbk, nullptr, ph, ph, nullptr,
                    NATOMS, HID, HID, KP_H, 0, 1);
    }

    // segment-mean pool (rounded), final projection (full precision out)
    pool_kernel<<<BG, 640>>>(batch);
    launch_gemm(ppool, ppwt, pb, nullptr, nullptr, (float*)d_out, nullptr,
                BG, HID, HID, KP_H, 0, 0);
}

// round 15
// speedup vs baseline: 1.1135x; 1.1135x over previous
#include <cuda_runtime.h>
#include <cuda_bf16.h>
#include <stdint.h>
#include <math.h>

#define NATOMS 10000
#define NEDGE  64000
#define BG     128
#define HID    600
#define NG     50
#define NL     6
#define HID4   150     // HID/4
#define KP_H   608     // HID padded to 16
#define KP_G   64      // NG padded to 16
#define TAB    4096    // W(d) table resolution
#define DMAX   8.6603f // > sqrt(75) = max possible distance
#define TDELTA (DMAX / (TAB - 1))

// ------------------------- scratch (static device globals) -------------------
__device__ int   g_ei0[NEDGE];
__device__ float g_efr[NEDGE];
__device__ float g_rbftab[TAB * KP_G];        // tf32-rounded
__device__ float g_Ctab  [TAB];
__device__ float g_F1tab [(size_t)NL * TAB * HID];
__device__ float g_Wtab  [(size_t)NL * TAB * HID];
__device__ float g_h  [NATOMS * HID];
__device__ float g_xjp[NATOMS * HID];
__device__ float g_agg[NATOMS * HID];
__device__ float g_t1 [NATOMS * HID];
__device__ float g_pool[BG * HID];

// tf32-rounded transposed weights (stored as f32): layout [N][Kpad]
__device__ float g_w1t [NL * HID * KP_G];
__device__ float g_w2t [NL * HID * KP_H];
__device__ float g_l1t [NL * HID * KP_H];
__device__ float g_l2t [NL * HID * KP_H];
__device__ float g_ilt [NL * HID * KP_H];
__device__ float g_pwt [HID * KP_H];

// ------------------------- helpers ------------------------------------------
__device__ __forceinline__ float sspf(float x) {
    float ax = fabsf(x);
    return fmaxf(x, 0.0f) + log1pf(expf(-ax)) - 0.69314718055994531f;
}

__device__ __forceinline__ float to_tf32(float x) {
    float r;
    asm("cvt.rna.tf32.f32 %0, %1;" : "=f"(r) : "f"(x));
    return r;
}

// ------------------------- edge geometry -> table coords ---------------------
__global__ void edge_geom_kernel(const float* __restrict__ pos,
                                 const int* __restrict__ src,
                                 const int* __restrict__ dst) {
    int e = blockIdx.x * blockDim.x + threadIdx.x;
    if (e >= NEDGE) return;
    int s = src[e], t = dst[e];
    float dx = pos[s*3+0] - pos[t*3+0];
    float dy = pos[s*3+1] - pos[t*3+1];
    float dz = pos[s*3+2] - pos[t*3+2];
    float d = sqrtf(dx*dx + dy*dy + dz*dz + 1e-12f);
    float tt = d * (1.0f / TDELTA);
    int i0 = (int)tt;
    if (i0 > TAB - 2) i0 = TAB - 2;
    g_ei0[e] = i0;
    g_efr[e] = tt - (float)i0;
}

// ------------------------- rbf + cutoff table (tf32-rounded) -----------------
__global__ void rbftab_kernel() {
    int i = blockIdx.x * blockDim.x + threadIdx.x;
    if (i >= TAB * KP_G) return;
    int r = i / KP_G;
    int g = i - r * KP_G;
    float d = (float)r * TDELTA;
    float v = 0.0f;
    if (g < NG) {
        float off = (float)g * (10.0f / 49.0f);
        float dd  = d - off;
        v = expf(-12.005f * dd * dd);
    }
    g_rbftab[i] = to_tf32(v);
    if (g == 0)
        g_Ctab[r] = 0.5f * (cosf(d * 0.31415926535897931f) + 1.0f);
}

__global__ void emb_kernel(const int* __restrict__ z, const float* __restrict__ emb) {
    int i = blockIdx.x * blockDim.x + threadIdx.x;
    if (i >= NATOMS * HID) return;
    int n = i / HID;
    int j = i - n * HID;
    g_h[i] = to_tf32(emb[z[n] * HID + j]);
}

// round a buffer in place to tf32 (float4 vectorized)
__global__ void round4_kernel(float* __restrict__ p, int n4) {
    int i = blockIdx.x * blockDim.x + threadIdx.x;
    if (i >= n4) return;
    float4 v = ((float4*)p)[i];
    v.x = to_tf32(v.x); v.y = to_tf32(v.y);
    v.z = to_tf32(v.z); v.w = to_tf32(v.w);
    ((float4*)p)[i] = v;
}

// ------------------------- weight transpose + tf32 round (batched) -----------
__global__ void convt_kernel(const float* __restrict__ in, float* __restrict__ out,
                             int K, int N, int Kpad,
                             long in_stride, long out_stride) {
    in  += (size_t)blockIdx.z * in_stride;
    out += (size_t)blockIdx.z * out_stride;
    __shared__ float tile[32][33];
    int kb = blockIdx.x * 32, nb = blockIdx.y * 32;
    int tx = threadIdx.x, ty = threadIdx.y;
    #pragma unroll
    for (int i = ty; i < 32; i += 8) {
        int k = kb + i, n = nb + tx;
        tile[i][tx] = (k < K && n < N) ? in[(size_t)k * N + n] : 0.0f;
    }
    __syncthreads();
    #pragma unroll
    for (int i = ty; i < 32; i += 8) {
        int n = nb + i, k = kb + tx;
        if (n < N && k < Kpad) out[(size_t)n * Kpad + k] = to_tf32(tile[tx][i]);
    }
}

// ------------------------- tf32 tensor-core GEMM (cp.async, grid.z batched) --
// Per batch z: C[M,N] = ep( A[M,K] @ Bt[N,Kpad] ), pointers offset by strides.
// CTA 128x128x16, 8 warps (2x4), warp tile 64x32, mma.m16n8k8, fp32 acc.
#define TBM 128
#define TBN 128
#define TBK 16
#define SA  20
#define SB  20

__global__ __launch_bounds__(256, 2)
void gemm_tc_kernel(const float* __restrict__ A,
                    const float* __restrict__ Bt,
                    const float* __restrict__ bias,
                    const float* __restrict__ rowscale,
                    const float* __restrict__ addsrc,
                    float* __restrict__ C,
                    float* __restrict__ zbuf,
                    int M, int N, int K, int Kpad, int do_ssp, int do_round,
                    long strideA, long strideB, long strideC, long strideBias) {
    A  += (size_t)blockIdx.z * strideA;
    Bt += (size_t)blockIdx.z * strideB;
    C  += (size_t)blockIdx.z * strideC;
    if (bias) bias += (size_t)blockIdx.z * strideBias;

    __shared__ __align__(16) float As[2][TBM * SA];
    __shared__ __align__(16) float Bs[2][TBN * SB];

    const int bm = blockIdx.y * TBM;
    const int bn = blockIdx.x * TBN;
    const int tid  = threadIdx.x;
    const int lane = tid & 31;
    const int warp = tid >> 5;
    const int wm0 = (warp >> 2) * 64;
    const int wn0 = (warp & 3) * 32;
    const int gid = lane >> 2;
    const int lk  = lane & 3;

    const int srow = tid >> 1;
    const int scol = (tid & 1) * 8;

    const uint32_t sAbase = (uint32_t)__cvta_generic_to_shared(&As[0][0]);
    const uint32_t sBbase = (uint32_t)__cvta_generic_to_shared(&Bs[0][0]);

    float acc[4][4][4] = {};

    const int nsteps = Kpad / TBK;

    auto stage = [&](int k0, int buf) {
        int gm = bm + srow;
        uint32_t da = sAbase + (uint32_t)((buf * TBM * SA + srow * SA + scol) * 4);
        const float* arow = A + (size_t)(gm < M ? gm : 0) * K;
        #pragma unroll
        for (int h2 = 0; h2 < 2; h2++) {
            int gk = k0 + scol + h2 * 4;
            int nb = (gm < M) ? (K - gk) * 4 : 0;
            nb = nb < 0 ? 0 : (nb > 16 ? 16 : nb);
            const float* gp = arow + (nb > 0 ? gk : 0);
            asm volatile("cp.async.cg.shared.global [%0], [%1], 16, %2;"
                         :: "r"(da + h2 * 16), "l"(gp), "r"(nb));
        }
        int gn = bn + srow;
        uint32_t db = sBbase + (uint32_t)((buf * TBN * SB + srow * SB + scol) * 4);
        const float* brow = Bt + (size_t)(gn < N ? gn : 0) * Kpad + k0 + scol;
        int nbB = (gn < N) ? 16 : 0;
        #pragma unroll
        for (int h2 = 0; h2 < 2; h2++) {
            asm volatile("cp.async.cg.shared.global [%0], [%1], 16, %2;"
                         :: "r"(db + h2 * 16), "l"(brow + h2 * 4), "r"(nbB));
        }
        asm volatile("cp.async.commit_group;" ::: "memory");
    };

    stage(0, 0);
    asm volatile("cp.async.wait_group 0;" ::: "memory");
    __syncthreads();

    for (int s = 0; s < nsteps; s++) {
        if (s + 1 < nsteps) stage((s + 1) * TBK, (s + 1) & 1);

        const float* as = As[s & 1];
        const float* bs = Bs[s & 1];
        #pragma unroll
        for (int ks = 0; ks < 2; ks++) {
            int kof = ks * 8 + lk;
            unsigned int af[4][4], bf[4][2];
            #pragma unroll
            for (int mt = 0; mt < 4; mt++) {
                int r = wm0 + mt * 16 + gid;
                af[mt][0] = __float_as_uint(as[r * SA + kof]);
                af[mt][1] = __float_as_uint(as[(r + 8) * SA + kof]);
                af[mt][2] = __float_as_uint(as[r * SA + kof + 4]);
                af[mt][3] = __float_as_uint(as[(r + 8) * SA + kof + 4]);
            }
            #pragma unroll
            for (int nt = 0; nt < 4; nt++) {
                int c = wn0 + nt * 8 + gid;
                bf[nt][0] = __float_as_uint(bs[c * SB + kof]);
                bf[nt][1] = __float_as_uint(bs[c * SB + kof + 4]);
            }
            #pragma unroll
            for (int mt = 0; mt < 4; mt++)
                #pragma unroll
                for (int nt = 0; nt < 4; nt++) {
                    asm volatile(
                        "mma.sync.aligned.m16n8k8.row.col.f32.tf32.tf32.f32 "
                        "{%0,%1,%2,%3}, {%4,%5,%6,%7}, {%8,%9}, {%0,%1,%2,%3};"
                        : "+f"(acc[mt][nt][0]), "+f"(acc[mt][nt][1]),
                          "+f"(acc[mt][nt][2]), "+f"(acc[mt][nt][3])
                        : "r"(af[mt][0]), "r"(af[mt][1]), "r"(af[mt][2]), "r"(af[mt][3]),
                          "r"(bf[nt][0]), "r"(bf[nt][1]));
                }
        }
        if (s + 1 < nsteps)
            asm volatile("cp.async.wait_group 0;" ::: "memory");
        __syncthreads();
    }

    // ---- epilogue ----
    #pragma unroll
    for (int mt = 0; mt < 4; mt++) {
        #pragma unroll
        for (int rr = 0; rr < 2; rr++) {
            int gm = bm + wm0 + mt * 16 + gid + rr * 8;
            if (gm >= M) continue;
            float rs = rowscale ? rowscale[gm] : 1.0f;
            #pragma unroll
            for (int nt = 0; nt < 4; nt++) {
                #pragma unroll
                for (int cc = 0; cc < 2; cc++) {
                    int gn = bn + wn0 + nt * 8 + lk * 2 + cc;
                    if (gn >= N) continue;
                    float v = acc[mt][nt][rr * 2 + cc];
                    if (bias) v += bias[gn];
                    if (do_ssp) v = sspf(v);
                    if (rowscale) v *= rs;
                    if (addsrc) v += addsrc[(size_t)gm * N + gn];
                    if (do_round) v = to_tf32(v);
                    C[(size_t)gm * N + gn] = v;
                    if (zbuf) zbuf[(size_t)gm * N + gn] = 0.0f;
                }
            }
        }
    }
}

// ------------------------- CFConv scatter with table interpolation -----------
__global__ void scatter_kernel(const int* __restrict__ src,
                               const int* __restrict__ dst,
                               const float* __restrict__ Wtab) {
    int i = blockIdx.x * blockDim.x + threadIdx.x;
    if (i >= NEDGE * HID4) return;
    int e = i / HID4;
    int j = i - e * HID4;
    int s = src[e], d = dst[e];
    int i0 = g_ei0[e];
    float f = g_efr[e];
    const float4* tp = (const float4*)Wtab;
    const float4* xp = (const float4*)g_xjp;
    float4 w0 = tp[(size_t)i0 * HID4 + j];
    float4 w1 = tp[(size_t)(i0 + 1) * HID4 + j];
    float4 x  = xp[(size_t)s * HID4 + j];
    float4 v;
    v.x = x.x * fmaf(f, w1.x - w0.x, w0.x);
    v.y = x.y * fmaf(f, w1.y - w0.y, w0.y);
    v.z = x.z * fmaf(f, w1.z - w0.z, w0.z);
    v.w = x.w * fmaf(f, w1.w - w0.w, w0.w);
    float* a = g_agg + ((size_t)d * HID + j * 4);
    asm volatile("red.global.add.v4.f32 [%0], {%1,%2,%3,%4};"
                 :: "l"(a), "f"(v.x), "f"(v.y), "f"(v.z), "f"(v.w) : "memory");
}

// ------------------------- segment-mean pool (rounded for final GEMM) --------
__global__ void pool_kernel(const int* __restrict__ batch) {
    int b = blockIdx.x;
    int t = threadIdx.x;
    int lo = 0, hi = NATOMS;
    while (lo < hi) { int mid = (lo + hi) >> 1; if (batch[mid] < b) lo = mid + 1; else hi = mid; }
    int start = lo;
    lo = start; hi = NATOMS;
    while (lo < hi) { int mid = (lo + hi) >> 1; if (batch[mid] <= b) lo = mid + 1; else hi = mid; }
    int end = lo;
    int cnt = end - start;
    float inv = cnt > 0 ? 1.0f / (float)cnt : 0.0f;
    if (t < HID) {
        float s = 0.0f;
        for (int n = start; n < end; n++) s += g_h[n * HID + t];
        g_pool[b * HID + t] = to_tf32(s * inv);
    }
}

// ------------------------- host orchestration --------------------------------
static inline void launch_gemm(const float* A, const float* Bt, const float* bias,
                               const float* rowscale, const float* addsrc,
                               float* C, float* zbuf, int M, int N, int K, int Kpad,
                               int do_ssp, int do_round,
                               int nbatch = 1, long sA = 0, long sB = 0,
                               long sC = 0, long sBias = 0) {
    dim3 grid((N + TBN - 1) / TBN, (M + TBM - 1) / TBM, nbatch);
    gemm_tc_kernel<<<grid, 256>>>(A, Bt, bias, rowscale, addsrc, C, zbuf,
                                  M, N, K, Kpad, do_ssp, do_round,
                                  sA, sB, sC, sBias);
}

static inline void launch_convt(const float* in, float* out, int K, int N, int Kpad,
                                long in_stride, long out_stride, int nbatch) {
    dim3 grid((Kpad + 31) / 32, (N + 31) / 32, nbatch);
    convt_kernel<<<grid, dim3(32, 8)>>>(in, out, K, N, Kpad, in_stride, out_stride);
}

extern "C" void kernel_launch(void* const* d_in, const int* in_sizes, int n_in,
                              void* d_out, int out_size) {
    const int*   z     = (const int*)  d_in[0];
    const float* pos   = (const float*)d_in[1];
    const int*   batch = (const int*)  d_in[2];
    const int*   ei    = (const int*)  d_in[3];
    const float* emb   = (const float*)d_in[4];
    const float* w1    = (const float*)d_in[5];
    const float* b1    = (const float*)d_in[6];
    const float* w2    = (const float*)d_in[7];
    const float* b2    = (const float*)d_in[8];
    const float* l1w   = (const float*)d_in[9];
    const float* l2w   = (const float*)d_in[10];
    const float* l2b   = (const float*)d_in[11];
    const float* ilw   = (const float*)d_in[12];
    const float* ilb   = (const float*)d_in[13];
    const float* pw    = (const float*)d_in[14];
    const float* pb    = (const float*)d_in[15];
    (void)in_sizes; (void)n_in; (void)out_size;

    const int* src = ei;
    const int* dst = ei + NEDGE;

    float *prbftab, *pCtab, *pF1tab, *pWtab, *ph, *pxjp, *pagg, *pt1, *ppool;
    float *pw1t, *pw2t, *pl1t, *pl2t, *pilt, *ppwt;
    cudaGetSymbolAddress((void**)&prbftab, g_rbftab);
    cudaGetSymbolAddress((void**)&pCtab,  g_Ctab);
    cudaGetSymbolAddress((void**)&pF1tab, g_F1tab);
    cudaGetSymbolAddress((void**)&pWtab,  g_Wtab);
    cudaGetSymbolAddress((void**)&ph,     g_h);
    cudaGetSymbolAddress((void**)&pxjp,   g_xjp);
    cudaGetSymbolAddress((void**)&pagg,   g_agg);
    cudaGetSymbolAddress((void**)&pt1,    g_t1);
    cudaGetSymbolAddress((void**)&ppool,  g_pool);
    cudaGetSymbolAddress((void**)&pw1t,   g_w1t);
    cudaGetSymbolAddress((void**)&pw2t,   g_w2t);
    cudaGetSymbolAddress((void**)&pl1t,   g_l1t);
    cudaGetSymbolAddress((void**)&pl2t,   g_l2t);
    cudaGetSymbolAddress((void**)&pilt,   g_ilt);
    cudaGetSymbolAddress((void**)&ppwt,   g_pwt);

    // weight transpose + tf32 rounding (batched over layers)
    launch_convt(w1,  pw1t, NG,  HID, KP_G, (long)NG  * HID, (long)HID * KP_G, NL);
    launch_convt(w2,  pw2t, HID, HID, KP_H, (long)HID * HID, (long)HID * KP_H, NL);
    launch_convt(l1w, pl1t, HID, HID, KP_H, (long)HID * HID, (long)HID * KP_H, NL);
    launch_convt(l2w, pl2t, HID, HID, KP_H, (long)HID * HID, (long)HID * KP_H, NL);
    launch_convt(ilw, pilt, HID, HID, KP_H, (long)HID * HID, (long)HID * KP_H, NL);
    launch_convt(pw,  ppwt, HID, HID, KP_H, 0, 0, 1);

    // edge table coords + rbf table + embedding init
    edge_geom_kernel<<<(NEDGE + 255) / 256, 256>>>(pos, src, dst);
    rbftab_kernel<<<(TAB * KP_G + 255) / 256, 256>>>();
    emb_kernel<<<(NATOMS * HID + 255) / 256, 256>>>(z, emb);

    // ---- precompute all layers' W(d) tables (independent of node chain) ----
    // F1tab[k] = ssp(rbftab @ w1[k] + b1[k]), tf32-rounded        [NL,TAB,H]
    launch_gemm(prbftab, pw1t, b1, nullptr, nullptr, pF1tab, nullptr,
                TAB, HID, KP_G, KP_G, 1, 1,
                NL, 0, (long)HID * KP_G, (long)TAB * HID, HID);
    // Wtab[k] = (F1tab[k] @ w2[k] + b2[k]) * Ctab                 [NL,TAB,H]
    launch_gemm(pF1tab, pw2t, b2, pCtab, nullptr, pWtab, nullptr,
                TAB, HID, HID, KP_H, 0, 0,
                NL, (long)TAB * HID, (long)HID * KP_H, (long)TAB * HID, HID);

    for (int k = 0; k < NL; k++) {
        const float* l2bk = l2b + (size_t)k * HID;
        const float* ilbk = ilb + (size_t)k * HID;
        const float* l1tk = pl1t + (size_t)k * HID * KP_H;
        const float* l2tk = pl2t + (size_t)k * HID * KP_H;
        const float* iltk = pilt + (size_t)k * HID * KP_H;
        const float* Wtabk = pWtab + (size_t)k * TAB * HID;

        // xjp = h @ lin1  (also zeroes agg in epilogue)          [N,H]
        launch_gemm(ph, l1tk, nullptr, nullptr, nullptr, pxjp, pagg,
                    NATOMS, HID, HID, KP_H, 0, 0);
        // agg += scatter(xjp[src] * W(d) -> dst)                 [N,H]
        scatter_kernel<<<(NEDGE * HID4 + 255) / 256, 256>>>(src, dst, Wtabk);
        round4_kernel<<<(NATOMS * HID4 + 255) / 256, 256>>>(pagg, NATOMS * HID4);
        // t1 = ssp(agg @ lin2 + lin2_b), tf32-rounded            [N,H]
        launch_gemm(pagg, l2tk, l2bk, nullptr, nullptr, pt1, nullptr,
                    NATOMS, HID, HID, KP_H, 1, 1);
        // h = h + t1 @ int_lin + int_b, tf32-rounded             [N,H]
        launch_gemm(pt1, iltk, ilbk, nullptr, ph, ph, nullptr,
                    NATOMS, HID, HID, KP_H, 0, 1);
    }

    // segment-mean pool (rounded), final projection (full precision out)
    pool_kernel<<<BG, 640>>>(batch);
    launch_gemm(ppool, ppwt, pb, nullptr, nullptr, (float*)d_out, nullptr,
                BG, HID, HID, KP_H, 0, 0);
}